// round 9
// baseline (speedup 1.0000x reference)
#include <cuda_runtime.h>
#include <cstdint>
#include <cstddef>

// Legacy-path (mma.sync m16n8k8.tf32) fused NeuralCTLSTM, v7:
// = v6 (m32 x n16 x 7g warp tile, 12 warps/CTA, 3/SMSP) with the WAR race
// fixed: the prefetch cp.async that overwrites the consumed stage is issued
// only AFTER all A-fragment LDS of that stage (p==1 branch, post-load).
// Warp-private 2-stage cp.async rings, no loop barriers.
// W (7x16x256 = 112KB) resident, pre-permuted. Grid (16, 9) = 144 CTAs.

#define NG 7
#define HH 256
#define BK 32
#define NCHUNK 8
#define THREADS 384
#define GYS 9
#define STREAMS (12 * GYS)                  // 108 warp-streams per o-block

#define W_BYTES (NG * NCHUNK * 2 * 2 * 512) // 224 frag-units x 512B = 114688
#define A_STAGE_B 4608                      // 32 rows x 36 floats x 4B
#define A_WARP_B (2 * A_STAGE_B)            // 9216
#define OFF_A W_BYTES
#define SMEM_BYTES (OFF_A + 12 * A_WARP_B)  // 225280

__device__ __forceinline__ uint32_t f2tf32(float f) {
    uint32_t u;
    asm("cvt.rna.tf32.f32 %0, %1;" : "=r"(u) : "f"(f));
    return u;
}

__device__ __forceinline__ void mma_tf32(float* d, const uint32_t* a,
                                         uint32_t b0, uint32_t b1) {
    asm volatile(
        "mma.sync.aligned.m16n8k8.row.col.f32.tf32.tf32.f32 "
        "{%0,%1,%2,%3}, {%4,%5,%6,%7}, {%8,%9}, {%0,%1,%2,%3};\n"
        : "+f"(d[0]), "+f"(d[1]), "+f"(d[2]), "+f"(d[3])
        : "r"(a[0]), "r"(a[1]), "r"(a[2]), "r"(a[3]), "r"(b0), "r"(b1));
}

__device__ __forceinline__ void cp_async16(uint32_t dst, const void* src) {
    asm volatile("cp.async.cg.shared.global [%0], [%1], 16;\n"
                 :: "r"(dst), "l"(src) : "memory");
}

__device__ __forceinline__ float tanh_fast(float x) {
    float y;
    asm("tanh.approx.f32 %0, %1;" : "=f"(y) : "f"(x));
    return y;
}
__device__ __forceinline__ float sigm(float x) {       // 0.5*tanh(x/2)+0.5
    return fmaf(tanh_fast(0.5f * x), 0.5f, 0.5f);
}

extern "C" __global__ void __launch_bounds__(THREADS, 1)
nctlstm_v7_kernel(const float* __restrict__ inter_times,
                  const float* __restrict__ h_ti,
                  const float* __restrict__ c_ti,
                  const float* __restrict__ cbar,
                  const float* __restrict__ W,
                  const float* __restrict__ bias,
                  float* __restrict__ out,
                  int Btot)
{
    extern __shared__ char smem[];
    const uint32_t sb = (uint32_t)__cvta_generic_to_shared(smem);

    const int tid  = threadIdx.x;
    const int warp = tid >> 5;       // 0..11
    const int lane = tid & 31;
    const int grp  = lane >> 2;      // 0..7
    const int tig  = lane & 3;       // 0..3

    const int o0 = blockIdx.x * 16;
    const int stream = blockIdx.y * 12 + warp;   // 0..107
    const int nblk = Btot >> 5;                  // 2048 32-row blocks

    const uint4* wperm = reinterpret_cast<const uint4*>(smem);
    uint4* wperm_w = reinterpret_cast<uint4*>(smem);
    const uint32_t warpA = sb + OFF_A + (uint32_t)warp * A_WARP_B;
    const float*  warpAf = reinterpret_cast<const float*>(smem + OFF_A + warp * A_WARP_B);

    // ---- warp-private A chunk loader: 32 rows x 32 cols, 8 cp.async/lane ----
    auto load_chunk = [&](int rb, int ch, int s) {
        const uint32_t ab = warpA + (uint32_t)s * A_STAGE_B;
        const float* src = h_ti + ((size_t)rb << 5) * HH + ch * BK;
#pragma unroll
        for (int i = 0; i < 8; i++) {
            const int idx = lane + i * 32;        // 0..255
            const int r = idx >> 3, c4 = idx & 7;
            cp_async16(ab + (uint32_t)(r * 144 + c4 * 16),
                       src + (size_t)r * HH + c4 * 4);
        }
        asm volatile("cp.async.commit_group;\n" ::: "memory");
    };

    // prologue: first two chunks of first block in flight during W permute
    const int rb0 = stream;
    load_chunk(rb0, 0, 0);
    load_chunk(rb0, 1, 1);

    // ---- one-time W permute (224 units, 12 warps cooperate) ----
    // unit u = (((g*8 + ch)*2 + p)*2 + nh); lane holds
    // W[g, o0+nh*8+grp, ch*32+p*16+tig+{0,4,8,12}] rna-rounded to tf32.
    for (int u = warp; u < NG * NCHUNK * 2 * 2; u += 12) {
        const int nh = u & 1, p = (u >> 1) & 1, ch = (u >> 2) & 7, g = u >> 5;
        const int o = o0 + nh * 8 + grp;
        const int k = ch * 32 + p * 16 + tig;
        const float* ws = W + ((size_t)g * HH + o) * HH + k;
        uint4 v;
        v.x = f2tf32(ws[0]);
        v.y = f2tf32(ws[4]);
        v.z = f2tf32(ws[8]);
        v.w = f2tf32(ws[12]);
        wperm_w[u * 32 + lane] = v;
    }

    // bias in registers (acc init)
    float2 bv[NG][2];
#pragma unroll
    for (int g = 0; g < NG; g++)
#pragma unroll
        for (int nh = 0; nh < 2; nh++)
            bv[g][nh] = *reinterpret_cast<const float2*>(
                bias + (size_t)g * HH + o0 + nh * 8 + 2 * tig);

    __syncthreads();   // W permute visible; only block barrier in the kernel

    const size_t BHtot = (size_t)Btot * HH;
    int s_cons = 0;

    for (int rb = rb0; rb < nblk; rb += STREAMS) {
        float acc[NG][2][2][4];          // [g][nh][mt][frag]
#pragma unroll
        for (int g = 0; g < NG; g++)
#pragma unroll
            for (int nh = 0; nh < 2; nh++)
#pragma unroll
                for (int mt = 0; mt < 2; mt++) {
                    acc[g][nh][mt][0] = bv[g][nh].x; acc[g][nh][mt][1] = bv[g][nh].y;
                    acc[g][nh][mt][2] = bv[g][nh].x; acc[g][nh][mt][3] = bv[g][nh].y;
                }

#pragma unroll 1
        for (int ch = 0; ch < NCHUNK; ch++) {
            asm volatile("cp.async.wait_group 1;\n" ::: "memory");

            const float* hs = warpAf + s_cons * (A_STAGE_B / 4);

#pragma unroll
            for (int p = 0; p < 2; p++) {
                // A fragments for this k-half only (16 live regs)
                uint32_t a[2][2][4];     // [q][mt][frag]
#pragma unroll
                for (int q = 0; q < 2; q++) {
                    const int k0 = (2 * p + q) * 8;
#pragma unroll
                    for (int mt = 0; mt < 2; mt++) {
                        const int r = mt * 16 + grp;
                        a[q][mt][0] = __float_as_uint(hs[r * 36 + k0 + tig]);
                        a[q][mt][1] = __float_as_uint(hs[(r + 8) * 36 + k0 + tig]);
                        a[q][mt][2] = __float_as_uint(hs[r * 36 + k0 + tig + 4]);
                        a[q][mt][3] = __float_as_uint(hs[(r + 8) * 36 + k0 + tig + 4]);
                    }
                }

                if (p == 1) {
                    // ALL LDS from stage s_cons are now issued (both halves);
                    // safe to overwrite it with the chunk ch+2 prefetch.
                    int c2 = ch + 2, r2 = rb;
                    if (c2 >= NCHUNK) { c2 -= NCHUNK; r2 += STREAMS; }
                    if (r2 < nblk) load_chunk(r2, c2, s_cons);
                    else           asm volatile("cp.async.commit_group;\n" ::: "memory");
                }

#pragma unroll
                for (int g = 0; g < NG; g++) {
#pragma unroll
                    for (int nh = 0; nh < 2; nh++) {
                        const uint4 wf =
                            wperm[((((g * 8 + ch) * 2 + p) * 2) + nh) * 32 + lane];
                        mma_tf32(acc[g][nh][0], a[0][0], wf.x, wf.y);
                        mma_tf32(acc[g][nh][1], a[0][1], wf.x, wf.y);
                        mma_tf32(acc[g][nh][0], a[1][0], wf.z, wf.w);
                        mma_tf32(acc[g][nh][1], a[1][1], wf.z, wf.w);
                    }
                }
            }
            s_cons ^= 1;
        }

        // ---- fused epilogue (warp-local; overlaps other warps' MMAs) ----
#pragma unroll
        for (int mt = 0; mt < 2; mt++) {
#pragma unroll
            for (int rs = 0; rs < 2; rs++) {
                const int b = rb * 32 + mt * 16 + grp + rs * 8;
                const float dt = __ldg(inter_times + b);
#pragma unroll
                for (int nh = 0; nh < 2; nh++) {
                    const size_t base = (size_t)b * HH + o0 + nh * 8 + 2 * tig;
                    const float2 cv = __ldcs(reinterpret_cast<const float2*>(c_ti + base));
                    const float2 cb = __ldcs(reinterpret_cast<const float2*>(cbar + base));

                    float2 r_o, r_h, r_c, r_cb, r_d;
#pragma unroll
                    for (int j = 0; j < 2; j++) {
                        const int ai = rs * 2 + j;
                        const float gi  = acc[0][nh][mt][ai];
                        const float gf  = acc[1][nh][mt][ai];
                        const float go  = acc[2][nh][mt][ai];
                        const float gib = acc[3][nh][mt][ai];
                        const float gfb = acc[4][nh][mt][ai];
                        const float gz  = acc[5][nh][mt][ai];
                        const float gd  = acc[6][nh][mt][ai];

                        const float i_g  = sigm(gi);
                        const float f_g  = sigm(gf);
                        const float o_g  = sigm(go);
                        const float ib_g = sigm(gib);
                        const float fb_g = sigm(gfb);
                        const float z    = tanh_fast(gz);
                        const float decay = fmaxf(gd, 0.0f)
                                          + __logf(1.0f + __expf(-fabsf(gd)));

                        const float ct  = (j == 0) ? cv.x : cv.y;
                        const float cbv = (j == 0) ? cb.x : cb.y;

                        const float e       = __expf(-decay * dt);
                        const float c_after = cbv + (ct - cbv) * e;
                        const float c_new   = f_g * c_after + i_g * z;
                        const float cb_new  = fb_g * cbv + ib_g * z;
                        const float h_new   = o_g * tanh_fast(c_after);

                        if (j == 0) { r_o.x = o_g; r_h.x = h_new; r_c.x = c_new; r_cb.x = cb_new; r_d.x = decay; }
                        else        { r_o.y = o_g; r_h.y = h_new; r_c.y = c_new; r_cb.y = cb_new; r_d.y = decay; }
                    }
                    __stcs(reinterpret_cast<float2*>(out + 0 * BHtot + base), r_o);
                    __stcs(reinterpret_cast<float2*>(out + 1 * BHtot + base), r_h);
                    __stcs(reinterpret_cast<float2*>(out + 2 * BHtot + base), r_c);
                    __stcs(reinterpret_cast<float2*>(out + 3 * BHtot + base), r_cb);
                    __stcs(reinterpret_cast<float2*>(out + 4 * BHtot + base), r_d);
                }
            }
        }
    }
}

extern "C" void kernel_launch(void* const* d_in, const int* in_sizes, int n_in,
                              void* d_out, int out_size)
{
    const float* inter_times = (const float*)d_in[0];
    const float* h_ti        = (const float*)d_in[1];
    const float* c_ti        = (const float*)d_in[2];
    const float* cbar        = (const float*)d_in[3];
    const float* W           = (const float*)d_in[4];
    const float* bias        = (const float*)d_in[5];
    const int B = in_sizes[0];

    cudaFuncSetAttribute(nctlstm_v7_kernel,
                         cudaFuncAttributeMaxDynamicSharedMemorySize, SMEM_BYTES);

    dim3 grid(16, GYS);   // 144 CTAs = one wave; one 16-col o-block per CTA
    nctlstm_v7_kernel<<<grid, THREADS, SMEM_BYTES>>>(
        inter_times, h_ti, c_ti, cbar, W, bias, (float*)d_out, B);
}

// round 11
// speedup vs baseline: 1.3289x; 1.3289x over previous
#include <cuda_runtime.h>
#include <cstdint>
#include <cstddef>

// Legacy-path (mma.sync m16n8k8.tf32) fused NeuralCTLSTM, v9:
// = v8 with the cp.async alignment bug fixed: the epilogue-operand staging
// buffer uses a 20-float (80B = 5x16B) row stride so every 16B cp.async
// destination is 16-aligned. Config otherwise = R7 best (8 warps,
// m32 x n16 x 7g, warp-private 2-stage rings, W 112KB resident) + staging
// of c_ti/cbar/inter_times through smem during chunk 0.
// Grid (16, 9) = 144 CTAs = one wave; 72 warp-streams per o-block.

#define NG 7
#define HH 256
#define BK 32
#define NCHUNK 8
#define THREADS 256
#define GYS 9
#define STREAMS (8 * GYS)                   // 72 warp-streams per o-block

#define W_BYTES (NG * NCHUNK * 2 * 2 * 512) // 224 frag-units x 512B = 114688
#define A_STAGE_B 4608                      // 32 rows x 36 floats x 4B
#define A_WARP_B (2 * A_STAGE_B)            // 9216
#define OFF_A W_BYTES
#define C_STRIDE_F 20                       // 80B row stride (16B-aligned)
#define C_ARR_B (32 * C_STRIDE_F * 4)       // 2560
#define C_WARP_B (2 * C_ARR_B + 128)        // c, cbar, dt = 5248
#define OFF_C (OFF_A + 8 * A_WARP_B)        // 188416
#define SMEM_BYTES (OFF_C + 8 * C_WARP_B)   // 230400

__device__ __forceinline__ uint32_t f2tf32(float f) {
    uint32_t u;
    asm("cvt.rna.tf32.f32 %0, %1;" : "=r"(u) : "f"(f));
    return u;
}

__device__ __forceinline__ void mma_tf32(float* d, const uint32_t* a,
                                         uint32_t b0, uint32_t b1) {
    asm volatile(
        "mma.sync.aligned.m16n8k8.row.col.f32.tf32.tf32.f32 "
        "{%0,%1,%2,%3}, {%4,%5,%6,%7}, {%8,%9}, {%0,%1,%2,%3};\n"
        : "+f"(d[0]), "+f"(d[1]), "+f"(d[2]), "+f"(d[3])
        : "r"(a[0]), "r"(a[1]), "r"(a[2]), "r"(a[3]), "r"(b0), "r"(b1));
}

__device__ __forceinline__ void cp_async16(uint32_t dst, const void* src) {
    asm volatile("cp.async.cg.shared.global [%0], [%1], 16;\n"
                 :: "r"(dst), "l"(src) : "memory");
}

__device__ __forceinline__ float tanh_fast(float x) {
    float y;
    asm("tanh.approx.f32 %0, %1;" : "=f"(y) : "f"(x));
    return y;
}
__device__ __forceinline__ float sigm(float x) {       // 0.5*tanh(x/2)+0.5
    return fmaf(tanh_fast(0.5f * x), 0.5f, 0.5f);
}

extern "C" __global__ void __launch_bounds__(THREADS, 1)
nctlstm_v9_kernel(const float* __restrict__ inter_times,
                  const float* __restrict__ h_ti,
                  const float* __restrict__ c_ti,
                  const float* __restrict__ cbar,
                  const float* __restrict__ W,
                  const float* __restrict__ bias,
                  float* __restrict__ out,
                  int Btot)
{
    extern __shared__ char smem[];
    const uint32_t sb = (uint32_t)__cvta_generic_to_shared(smem);

    const int tid  = threadIdx.x;
    const int warp = tid >> 5;       // 0..7
    const int lane = tid & 31;
    const int grp  = lane >> 2;      // 0..7
    const int tig  = lane & 3;       // 0..3

    const int o0 = blockIdx.x * 16;
    const int stream = blockIdx.y * 8 + warp;    // 0..71
    const int nblk = Btot >> 5;                  // 2048 32-row blocks

    const uint4* wperm = reinterpret_cast<const uint4*>(smem);
    uint4* wperm_w = reinterpret_cast<uint4*>(smem);
    const uint32_t warpA = sb + OFF_A + (uint32_t)warp * A_WARP_B;
    const float*  warpAf = reinterpret_cast<const float*>(smem + OFF_A + warp * A_WARP_B);
    const uint32_t warpC = sb + OFF_C + (uint32_t)warp * C_WARP_B;
    const float*  c_s  = reinterpret_cast<const float*>(smem + OFF_C + warp * C_WARP_B);
    const float*  cb_s = c_s + (C_ARR_B / 4);
    const float*  dt_s = cb_s + (C_ARR_B / 4);

    // ---- warp-private A chunk loader: 32 rows x 32 cols, 8 cp.async/lane ----
    auto load_chunk = [&](int rb, int ch, int s) {
        const uint32_t ab = warpA + (uint32_t)s * A_STAGE_B;
        const float* src = h_ti + ((size_t)rb << 5) * HH + ch * BK;
#pragma unroll
        for (int i = 0; i < 8; i++) {
            const int idx = lane + i * 32;        // 0..255
            const int r = idx >> 3, c4 = idx & 7;
            cp_async16(ab + (uint32_t)(r * 144 + c4 * 16),
                       src + (size_t)r * HH + c4 * 4);
        }
        asm volatile("cp.async.commit_group;\n" ::: "memory");
    };

    // ---- epilogue-operand stager (NO commit; joins caller's group) ----
    // c_ti / cbar: 32 rows x 16 floats each, row stride 20 floats (80B,
    // every 16B granule dst 16-aligned); dt: 32 floats.
    auto load_cblock = [&](int rb) {
        const float* csrc  = c_ti + ((size_t)rb << 5) * HH + o0;
        const float* cbsrc = cbar + ((size_t)rb << 5) * HH + o0;
#pragma unroll
        for (int i = 0; i < 4; i++) {
            const int idx = lane + i * 32;        // 0..127
            const int r = idx >> 2, cg = idx & 3;
            cp_async16(warpC + (uint32_t)(r * (C_STRIDE_F * 4) + cg * 16),
                       csrc + (size_t)r * HH + cg * 4);
            cp_async16(warpC + (uint32_t)(C_ARR_B + r * (C_STRIDE_F * 4) + cg * 16),
                       cbsrc + (size_t)r * HH + cg * 4);
        }
        if (lane < 8)
            cp_async16(warpC + (uint32_t)(2 * C_ARR_B + lane * 16),
                       inter_times + (rb << 5) + lane * 4);
    };

    // prologue: first two chunks of first block in flight during W permute
    const int rb0 = stream;
    load_chunk(rb0, 0, 0);
    load_chunk(rb0, 1, 1);

    // ---- one-time W permute (224 units, 8 warps cooperate) ----
    for (int u = warp; u < NG * NCHUNK * 2 * 2; u += 8) {
        const int nh = u & 1, p = (u >> 1) & 1, ch = (u >> 2) & 7, g = u >> 5;
        const int o = o0 + nh * 8 + grp;
        const int k = ch * 32 + p * 16 + tig;
        const float* ws = W + ((size_t)g * HH + o) * HH + k;
        uint4 v;
        v.x = f2tf32(ws[0]);
        v.y = f2tf32(ws[4]);
        v.z = f2tf32(ws[8]);
        v.w = f2tf32(ws[12]);
        wperm_w[u * 32 + lane] = v;
    }

    // bias in registers (acc init)
    float2 bv[NG][2];
#pragma unroll
    for (int g = 0; g < NG; g++)
#pragma unroll
        for (int nh = 0; nh < 2; nh++)
            bv[g][nh] = *reinterpret_cast<const float2*>(
                bias + (size_t)g * HH + o0 + nh * 8 + 2 * tig);

    __syncthreads();   // W permute visible; only block barrier in the kernel

    const size_t BHtot = (size_t)Btot * HH;
    int s_cons = 0;

    for (int rb = rb0; rb < nblk; rb += STREAMS) {
        float acc[NG][2][2][4];          // [g][nh][mt][frag]
#pragma unroll
        for (int g = 0; g < NG; g++)
#pragma unroll
            for (int nh = 0; nh < 2; nh++)
#pragma unroll
                for (int mt = 0; mt < 2; mt++) {
                    acc[g][nh][mt][0] = bv[g][nh].x; acc[g][nh][mt][1] = bv[g][nh].y;
                    acc[g][nh][mt][2] = bv[g][nh].x; acc[g][nh][mt][3] = bv[g][nh].y;
                }

#pragma unroll 1
        for (int ch = 0; ch < NCHUNK; ch++) {
            asm volatile("cp.async.wait_group 1;\n" ::: "memory");

            const float* hs = warpAf + s_cons * (A_STAGE_B / 4);

            // load ALL A fragments for this chunk first (32 regs)
            uint32_t a[2][2][2][4];      // [p][q][mt][frag]
#pragma unroll
            for (int p = 0; p < 2; p++)
#pragma unroll
                for (int q = 0; q < 2; q++) {
                    const int k0 = (2 * p + q) * 8;
#pragma unroll
                    for (int mt = 0; mt < 2; mt++) {
                        const int r = mt * 16 + grp;
                        a[p][q][mt][0] = __float_as_uint(hs[r * 36 + k0 + tig]);
                        a[p][q][mt][1] = __float_as_uint(hs[(r + 8) * 36 + k0 + tig]);
                        a[p][q][mt][2] = __float_as_uint(hs[r * 36 + k0 + tig + 4]);
                        a[p][q][mt][3] = __float_as_uint(hs[(r + 8) * 36 + k0 + tig + 4]);
                    }
                }

            // all LDS from stage s_cons issued: safe to overwrite it.
            // chunk 0 also stages this block's epilogue operands (same group).
            {
                if (ch == 0) load_cblock(rb);
                int c2 = ch + 2, r2 = rb;
                if (c2 >= NCHUNK) { c2 -= NCHUNK; r2 += STREAMS; }
                if (r2 < nblk) load_chunk(r2, c2, s_cons);
                else           asm volatile("cp.async.commit_group;\n" ::: "memory");
            }
            s_cons ^= 1;

            // 28 LDS.128 (W frags) + 112 HMMA
#pragma unroll
            for (int p = 0; p < 2; p++) {
#pragma unroll
                for (int g = 0; g < NG; g++) {
#pragma unroll
                    for (int nh = 0; nh < 2; nh++) {
                        const uint4 wf =
                            wperm[((((g * 8 + ch) * 2 + p) * 2) + nh) * 32 + lane];
                        mma_tf32(acc[g][nh][0], a[p][0][0], wf.x, wf.y);
                        mma_tf32(acc[g][nh][1], a[p][0][1], wf.x, wf.y);
                        mma_tf32(acc[g][nh][0], a[p][1][0], wf.z, wf.w);
                        mma_tf32(acc[g][nh][1], a[p][1][1], wf.z, wf.w);
                    }
                }
            }
        }

        // ---- fused epilogue: all operands in smem (staged in chunk 0) ----
#pragma unroll
        for (int mt = 0; mt < 2; mt++) {
#pragma unroll
            for (int rs = 0; rs < 2; rs++) {
                const int row = mt * 16 + grp + rs * 8;       // 0..31
                const int b = rb * 32 + row;
                const float dt = dt_s[row];
#pragma unroll
                for (int nh = 0; nh < 2; nh++) {
                    const int col = nh * 8 + 2 * tig;
                    const float2 cv = *reinterpret_cast<const float2*>(
                        c_s + row * C_STRIDE_F + col);
                    const float2 cb = *reinterpret_cast<const float2*>(
                        cb_s + row * C_STRIDE_F + col);
                    const size_t base = (size_t)b * HH + o0 + col;

                    float2 r_o, r_h, r_c, r_cb, r_d;
#pragma unroll
                    for (int j = 0; j < 2; j++) {
                        const int ai = rs * 2 + j;
                        const float gi  = acc[0][nh][mt][ai];
                        const float gf  = acc[1][nh][mt][ai];
                        const float go  = acc[2][nh][mt][ai];
                        const float gib = acc[3][nh][mt][ai];
                        const float gfb = acc[4][nh][mt][ai];
                        const float gz  = acc[5][nh][mt][ai];
                        const float gd  = acc[6][nh][mt][ai];

                        const float i_g  = sigm(gi);
                        const float f_g  = sigm(gf);
                        const float o_g  = sigm(go);
                        const float ib_g = sigm(gib);
                        const float fb_g = sigm(gfb);
                        const float z    = tanh_fast(gz);
                        const float decay = fmaxf(gd, 0.0f)
                                          + __logf(1.0f + __expf(-fabsf(gd)));

                        const float ct  = (j == 0) ? cv.x : cv.y;
                        const float cbv = (j == 0) ? cb.x : cb.y;

                        const float e       = __expf(-decay * dt);
                        const float c_after = cbv + (ct - cbv) * e;
                        const float c_new   = f_g * c_after + i_g * z;
                        const float cb_new  = fb_g * cbv + ib_g * z;
                        const float h_new   = o_g * tanh_fast(c_after);

                        if (j == 0) { r_o.x = o_g; r_h.x = h_new; r_c.x = c_new; r_cb.x = cb_new; r_d.x = decay; }
                        else        { r_o.y = o_g; r_h.y = h_new; r_c.y = c_new; r_cb.y = cb_new; r_d.y = decay; }
                    }
                    __stcs(reinterpret_cast<float2*>(out + 0 * BHtot + base), r_o);
                    __stcs(reinterpret_cast<float2*>(out + 1 * BHtot + base), r_h);
                    __stcs(reinterpret_cast<float2*>(out + 2 * BHtot + base), r_c);
                    __stcs(reinterpret_cast<float2*>(out + 3 * BHtot + base), r_cb);
                    __stcs(reinterpret_cast<float2*>(out + 4 * BHtot + base), r_d);
                }
            }
        }
    }
}

extern "C" void kernel_launch(void* const* d_in, const int* in_sizes, int n_in,
                              void* d_out, int out_size)
{
    const float* inter_times = (const float*)d_in[0];
    const float* h_ti        = (const float*)d_in[1];
    const float* c_ti        = (const float*)d_in[2];
    const float* cbar        = (const float*)d_in[3];
    const float* W           = (const float*)d_in[4];
    const float* bias        = (const float*)d_in[5];
    const int B = in_sizes[0];

    cudaFuncSetAttribute(nctlstm_v9_kernel,
                         cudaFuncAttributeMaxDynamicSharedMemorySize, SMEM_BYTES);

    dim3 grid(16, GYS);   // 144 CTAs = one wave; one 16-col o-block per CTA
    nctlstm_v9_kernel<<<grid, THREADS, SMEM_BYTES>>>(
        inter_times, h_ti, c_ti, cbar, W, bias, (float*)d_out, B);
}